// round 4
// baseline (speedup 1.0000x reference)
#include <cuda_runtime.h>

#define NNODES 50000
#define NEDGES 400000
#define FEAT   64
#define HEADS  4

// ---------------- scratch (static device globals; no allocation) ----------------
__device__ float g_Qp[(size_t)NNODES * 256];   // Q' = x @ M_h, layout [n][h*64+d]
__device__ float g_T [(size_t)NNODES * 256];   // segment-softmax-weighted sums of x_s
__device__ float g_M [HEADS * 64 * 64];        // M_h pair-interleaved: [h][k/2][c][k&1]
__device__ float g_Wst[256 * 64];              // Wst pair-interleaved: [k/2][c][k&1]
__device__ int   g_deg   [NNODES];
__device__ int   g_rowptr[NNODES + 1];
__device__ int   g_cursor[NNODES];
__device__ int   g_esend [NEDGES];
__device__ int   g_bsum  [64];
__device__ int   g_bsumx [64];

// packed f32x2 helpers
#define FMA2(acc, a, b) asm("fma.rn.f32x2 %0, %1, %2, %0;" : "+l"(acc) : "l"(a), "l"(b))
#define UNPACK2(lo, hi, v) asm("mov.b64 {%0, %1}, %2;" : "=f"(lo), "=f"(hi) : "l"(v))

// ---------------- small matrix prep ----------------
// blocks 0..3: M_h = Wq_h @ Wk_h^T * 0.125   (stored k-pair interleaved)
// blocks 4..7: Wst  = Wv_h @ Wout * 0.25     (stored k-pair interleaved)
__global__ __launch_bounds__(256) void prep_mats_kernel(
    const float* __restrict__ Wq, const float* __restrict__ Wk,
    const float* __restrict__ Wv, const float* __restrict__ Wout)
{
    __shared__ float As[64 * 65];
    __shared__ float Bs[64 * 65];
    int b = blockIdx.x;
    int tid = threadIdx.x;

    if (b < 4) {
        int h = b;
        const float* A = Wq + h * 4096;
        const float* B = Wk + h * 4096;
        for (int i = tid; i < 4096; i += 256) {
            As[(i >> 6) * 65 + (i & 63)] = A[i];
            Bs[(i >> 6) * 65 + (i & 63)] = B[i];
        }
        __syncthreads();
        for (int o = tid; o < 4096; o += 256) {
            int k = o & 63, c = o >> 6;       // k = f1 (contraction), c = f2 (output col)
            float s = 0.f;
            #pragma unroll 8
            for (int d = 0; d < 64; d++)
                s += As[k * 65 + d] * Bs[c * 65 + d];
            // pair-interleaved store: [h][k>>1][c][k&1]
            g_M[h * 4096 + (k >> 1) * 128 + (c << 1) + (k & 1)] = s * 0.125f;
        }
    } else {
        int h = b - 4;
        const float* A = Wv + h * 4096;
        for (int i = tid; i < 4096; i += 256) {
            As[(i >> 6) * 65 + (i & 63)] = A[i];
            Bs[(i >> 6) * 65 + (i & 63)] = Wout[i];
        }
        __syncthreads();
        for (int o = tid; o < 4096; o += 256) {
            int f = o & 63, c = o >> 6;
            float s = 0.f;
            #pragma unroll 8
            for (int d = 0; d < 64; d++)
                s += As[f * 65 + d] * Bs[d * 65 + c];
            int k = h * 64 + f;               // contraction index 0..255
            g_Wst[(k >> 1) * 128 + (c << 1) + (k & 1)] = s * 0.25f;
        }
    }
}

// ---------------- CSR build ----------------
__global__ void zero_deg_kernel(int n) {
    int i = blockIdx.x * blockDim.x + threadIdx.x;
    if (i < n) g_deg[i] = 0;
}

__global__ void count_deg_kernel(const int* __restrict__ recv, int E) {
    int i = blockIdx.x * blockDim.x + threadIdx.x;
    if (i < E) atomicAdd(&g_deg[recv[i]], 1);
}

__global__ __launch_bounds__(1024) void scan_blocks_kernel(int n) {
    __shared__ int wsum[32];
    int b = blockIdx.x;
    int tid = threadIdx.x, lane = tid & 31, wid = tid >> 5;
    int i = (b << 10) + tid;
    int v = (i < n) ? g_deg[i] : 0;
    int xi = v;
    #pragma unroll
    for (int o = 1; o < 32; o <<= 1) {
        int t = __shfl_up_sync(0xffffffffu, xi, o);
        if (lane >= o) xi += t;
    }
    if (lane == 31) wsum[wid] = xi;
    __syncthreads();
    if (wid == 0) {
        int s = wsum[lane];
        #pragma unroll
        for (int o = 1; o < 32; o <<= 1) {
            int t = __shfl_up_sync(0xffffffffu, s, o);
            if (lane >= o) s += t;
        }
        wsum[lane] = s;
    }
    __syncthreads();
    int incl = xi + (wid ? wsum[wid - 1] : 0);
    if (i < n) g_rowptr[i] = incl - v;
    if (tid == 1023) g_bsum[b] = incl;
}

__global__ __launch_bounds__(32) void scan_tops_kernel(int nb, int n) {
    int lane = threadIdx.x;
    int v0 = (lane < nb) ? g_bsum[lane] : 0;
    int v1 = (lane + 32 < nb) ? g_bsum[lane + 32] : 0;
    int s0 = v0;
    #pragma unroll
    for (int o = 1; o < 32; o <<= 1) {
        int t = __shfl_up_sync(0xffffffffu, s0, o);
        if (lane >= o) s0 += t;
    }
    int tot0 = __shfl_sync(0xffffffffu, s0, 31);
    int s1 = v1;
    #pragma unroll
    for (int o = 1; o < 32; o <<= 1) {
        int t = __shfl_up_sync(0xffffffffu, s1, o);
        if (lane >= o) s1 += t;
    }
    s1 += tot0;
    g_bsumx[lane] = s0 - v0;
    g_bsumx[lane + 32] = s1 - v1;
    if (lane == 31) g_rowptr[n] = s1;
}

__global__ __launch_bounds__(1024) void scan_add_kernel(int n) {
    int i = (blockIdx.x << 10) + threadIdx.x;
    if (i < n) {
        int r = g_rowptr[i] + g_bsumx[blockIdx.x];
        g_rowptr[i] = r;
        g_cursor[i] = r;
    }
}

__global__ void scatter_edges_kernel(const int* __restrict__ send,
                                     const int* __restrict__ recv, int E) {
    int i = blockIdx.x * blockDim.x + threadIdx.x;
    if (i < E) {
        int pos = atomicAdd(&g_cursor[recv[i]], 1);
        g_esend[pos] = send[i];
    }
}

// ---------------- GEMM 1: Q' = x @ M_h  (per head) ----------------
// mov-free f32x2: k-pair split accumulators. Thread (rg,cg): rows rg*8..+7,
// cols {cg, cg+16, cg+32, cg+48}. Inner 2-k step: 12 LDS.64 + 32 FFMA2.
__global__ __launch_bounds__(256) void gemm_qp_kernel(const float* __restrict__ x, int n) {
    __shared__ float As[128][68];                 // padded: float4-aligned rows
    __shared__ unsigned long long Bs[32][64];     // Bs[k2][c] = {M[2k2][c], M[2k2+1][c]}
    int h = blockIdx.y;
    int row0 = blockIdx.x * 128;
    int tid = threadIdx.x;

    const unsigned long long* Bg =
        reinterpret_cast<const unsigned long long*>(g_M + h * 4096);
    for (int i = tid; i < 2048; i += 256)
        (&Bs[0][0])[i] = Bg[i];

    for (int i = tid; i < 2048; i += 256) {
        int r = i >> 4, k4 = (i & 15) << 2;
        int gr = row0 + r;
        float4 v = make_float4(0.f, 0.f, 0.f, 0.f);
        if (gr < n) v = *reinterpret_cast<const float4*>(x + (size_t)gr * 64 + k4);
        *reinterpret_cast<float4*>(&As[r][k4]) = v;
    }
    __syncthreads();

    int rg = tid >> 4;   // 0..15
    int cg = tid & 15;   // 0..15
    unsigned long long acc[8][4];
    #pragma unroll
    for (int i = 0; i < 8; i++)
        #pragma unroll
        for (int j = 0; j < 4; j++) acc[i][j] = 0ull;

    #pragma unroll 4
    for (int k2 = 0; k2 < 32; k2++) {
        unsigned long long b0 = Bs[k2][cg];
        unsigned long long b1 = Bs[k2][cg + 16];
        unsigned long long b2 = Bs[k2][cg + 32];
        unsigned long long b3 = Bs[k2][cg + 48];
        #pragma unroll
        for (int i = 0; i < 8; i++) {
            unsigned long long a =
                *reinterpret_cast<const unsigned long long*>(&As[(rg << 3) + i][k2 << 1]);
            FMA2(acc[i][0], a, b0);
            FMA2(acc[i][1], a, b1);
            FMA2(acc[i][2], a, b2);
            FMA2(acc[i][3], a, b3);
        }
    }

    #pragma unroll
    for (int i = 0; i < 8; i++) {
        int gr = row0 + (rg << 3) + i;
        if (gr < n) {
            float* dst = g_Qp + (size_t)gr * 256 + h * 64 + cg;
            #pragma unroll
            for (int j = 0; j < 4; j++) {
                float lo, hi;
                UNPACK2(lo, hi, acc[i][j]);
                dst[j << 4] = lo + hi;
            }
        }
    }
}

// ---------------- fused attention: segment softmax (no-shift) + weighted sum ----------------
// one warp per receiver; lane l: head h=l/8, feature chunk (l%8)*8..+7
__global__ __launch_bounds__(256) void attn_kernel(const float* __restrict__ x, int n) {
    int r = (blockIdx.x << 3) + (threadIdx.x >> 5);
    if (r >= n) return;
    int lane = threadIdx.x & 31;
    int j = lane & 7;

    const float4* qr = reinterpret_cast<const float4*>(g_Qp + (size_t)r * 256);
    float4 q0 = qr[lane * 2], q1 = qr[lane * 2 + 1];

    int beg = g_rowptr[r], end = g_rowptr[r + 1];
    float dsum = 0.f;
    float4 a0 = make_float4(0.f, 0.f, 0.f, 0.f);
    float4 a1 = a0;

    // scores s = x_r^T M_h x_s are O(1) (|s| << 80), so unshifted exp is safe
    // in fp32 and mathematically identical to the max-shifted softmax.
    #pragma unroll 2
    for (int p = beg; p < end; p++) {
        int s = g_esend[p];
        const float4* xs = reinterpret_cast<const float4*>(x + (size_t)s * 64);
        float4 v0 = xs[j * 2], v1 = xs[j * 2 + 1];

        float part = q0.x * v0.x + q0.y * v0.y + q0.z * v0.z + q0.w * v0.w
                   + q1.x * v1.x + q1.y * v1.y + q1.z * v1.z + q1.w * v1.w;
        part += __shfl_xor_sync(0xffffffffu, part, 1);
        part += __shfl_xor_sync(0xffffffffu, part, 2);
        part += __shfl_xor_sync(0xffffffffu, part, 4);

        float pe = __expf(part);
        dsum += pe;
        a0.x += pe * v0.x; a0.y += pe * v0.y; a0.z += pe * v0.z; a0.w += pe * v0.w;
        a1.x += pe * v1.x; a1.y += pe * v1.y; a1.z += pe * v1.z; a1.w += pe * v1.w;
    }

    float rinv = (dsum > 0.f) ? (1.0f / dsum) : 0.f;
    a0.x *= rinv; a0.y *= rinv; a0.z *= rinv; a0.w *= rinv;
    a1.x *= rinv; a1.y *= rinv; a1.z *= rinv; a1.w *= rinv;

    float4* tr = reinterpret_cast<float4*>(g_T + (size_t)r * 256);
    tr[lane * 2] = a0;
    tr[lane * 2 + 1] = a1;
}

// ---------------- GEMM 2: out = x + T @ Wst  (N x 256)@(256 x 64) ----------------
__global__ __launch_bounds__(256) void gemm_out_kernel(const float* __restrict__ x,
                                                       float* __restrict__ out, int n) {
    __shared__ float As[128][68];
    __shared__ unsigned long long Bs[32][64];
    int row0 = blockIdx.x * 128;
    int tid = threadIdx.x;
    int rg = tid >> 4, cg = tid & 15;

    unsigned long long acc[8][4];
    #pragma unroll
    for (int i = 0; i < 8; i++)
        #pragma unroll
        for (int j = 0; j < 4; j++) acc[i][j] = 0ull;

    const unsigned long long* Bg = reinterpret_cast<const unsigned long long*>(g_Wst);

    for (int kc = 0; kc < 4; kc++) {
        for (int i = tid; i < 2048; i += 256)
            (&Bs[0][0])[i] = Bg[kc * 2048 + i];
        for (int i = tid; i < 2048; i += 256) {
            int r = i >> 4, k4 = (i & 15) << 2;
            int gr = row0 + r;
            float4 v = make_float4(0.f, 0.f, 0.f, 0.f);
            if (gr < n)
                v = *reinterpret_cast<const float4*>(g_T + (size_t)gr * 256 + kc * 64 + k4);
            *reinterpret_cast<float4*>(&As[r][k4]) = v;
        }
        __syncthreads();

        #pragma unroll 4
        for (int k2 = 0; k2 < 32; k2++) {
            unsigned long long b0 = Bs[k2][cg];
            unsigned long long b1 = Bs[k2][cg + 16];
            unsigned long long b2 = Bs[k2][cg + 32];
            unsigned long long b3 = Bs[k2][cg + 48];
            #pragma unroll
            for (int i = 0; i < 8; i++) {
                unsigned long long a =
                    *reinterpret_cast<const unsigned long long*>(&As[(rg << 3) + i][k2 << 1]);
                FMA2(acc[i][0], a, b0);
                FMA2(acc[i][1], a, b1);
                FMA2(acc[i][2], a, b2);
                FMA2(acc[i][3], a, b3);
            }
        }
        __syncthreads();
    }

    #pragma unroll
    for (int i = 0; i < 8; i++) {
        int gr = row0 + (rg << 3) + i;
        if (gr < n) {
            const float* xr = x + (size_t)gr * 64 + cg;
            float* dst = out + (size_t)gr * 64 + cg;
            #pragma unroll
            for (int j = 0; j < 4; j++) {
                float lo, hi;
                UNPACK2(lo, hi, acc[i][j]);
                dst[j << 4] = lo + hi + xr[j << 4];
            }
        }
    }
}

// ---------------- launch ----------------
extern "C" void kernel_launch(void* const* d_in, const int* in_sizes, int n_in,
                              void* d_out, int out_size) {
    const float* x    = (const float*)d_in[0];
    const float* Wq   = (const float*)d_in[1];
    const float* Wk   = (const float*)d_in[2];
    const float* Wv   = (const float*)d_in[3];
    const float* Wout = (const float*)d_in[4];
    const int*   ei   = (const int*)d_in[5];

    int n = in_sizes[0] / FEAT;       // 50000
    int E = in_sizes[5] / 2;          // 400000
    const int* send = ei;
    const int* recv = ei + E;
    int nb = (n + 1023) / 1024;       // 49

    prep_mats_kernel<<<8, 256>>>(Wq, Wk, Wv, Wout);

    zero_deg_kernel<<<(n + 511) / 512, 512>>>(n);
    count_deg_kernel<<<(E + 511) / 512, 512>>>(recv, E);
    scan_blocks_kernel<<<nb, 1024>>>(n);
    scan_tops_kernel<<<1, 32>>>(nb, n);
    scan_add_kernel<<<nb, 1024>>>(n);
    scatter_edges_kernel<<<(E + 511) / 512, 512>>>(send, recv, E);

    dim3 g1((n + 127) / 128, HEADS);
    gemm_qp_kernel<<<g1, 256>>>(x, n);

    attn_kernel<<<(n + 7) / 8, 256>>>(x, n);

    gemm_out_kernel<<<(n + 127) / 128, 256>>>(x, (float*)d_out, n);
}

// round 5
// speedup vs baseline: 1.1991x; 1.1991x over previous
#include <cuda_runtime.h>

#define NNODES 50000
#define NEDGES 400000
#define FEAT   64
#define HEADS  4

// ---------------- scratch (static device globals; no allocation) ----------------
__device__ float g_Qp[(size_t)NNODES * 256];   // Q' = x @ M_h, layout [n][h*64+d]
__device__ float g_T [(size_t)NNODES * 256];   // segment-softmax-weighted sums of x_s
__device__ float g_M [HEADS * 64 * 64];        // M_h = Wq_h @ Wk_h^T * scale, [h][k][c]
__device__ float g_Wst[256 * 64];              // Wst[h*64+f][c] = (Wv_h @ Wout)[f][c] / 4
__device__ int   g_deg   [NNODES];
__device__ int   g_rowptr[NNODES + 1];
__device__ int   g_cursor[NNODES];
__device__ int   g_esend [NEDGES];
__device__ int   g_bsum  [64];
__device__ int   g_bsumx [64];

// packed f32x2 helpers
#define FMA2(acc, a, b) asm("fma.rn.f32x2 %0, %1, %2, %0;" : "+l"(acc) : "l"(a), "l"(b))
#define ADD2(d, a, b)   asm("add.rn.f32x2 %0, %1, %2;" : "=l"(d) : "l"(a), "l"(b))
#define DUP2(d, a)      asm("mov.b64 %0, {%1, %1};" : "=l"(d) : "r"(a))

// ---------------- small matrix prep ----------------
__global__ __launch_bounds__(256) void prep_mats_kernel(
    const float* __restrict__ Wq, const float* __restrict__ Wk,
    const float* __restrict__ Wv, const float* __restrict__ Wout)
{
    __shared__ float As[64 * 65];
    __shared__ float Bs[64 * 65];
    int b = blockIdx.x;
    int tid = threadIdx.x;

    if (b < 4) {
        int h = b;
        const float* A = Wq + h * 4096;
        const float* B = Wk + h * 4096;
        for (int i = tid; i < 4096; i += 256) {
            As[(i >> 6) * 65 + (i & 63)] = A[i];
            Bs[(i >> 6) * 65 + (i & 63)] = B[i];
        }
        __syncthreads();
        // M[f1][f2] = sum_d Wq[f1][d]*Wk[f2][d] * 0.125
        for (int o = tid; o < 4096; o += 256) {
            int f1 = o & 63, f2 = o >> 6;
            float s = 0.f;
            #pragma unroll 8
            for (int d = 0; d < 64; d++)
                s += As[f1 * 65 + d] * Bs[f2 * 65 + d];
            g_M[h * 4096 + f1 * 64 + f2] = s * 0.125f;
        }
    } else {
        int h = b - 4;
        const float* A = Wv + h * 4096;
        for (int i = tid; i < 4096; i += 256) {
            As[(i >> 6) * 65 + (i & 63)] = A[i];
            Bs[(i >> 6) * 65 + (i & 63)] = Wout[i];
        }
        __syncthreads();
        for (int o = tid; o < 4096; o += 256) {
            int f = o & 63, c = o >> 6;
            float s = 0.f;
            #pragma unroll 8
            for (int d = 0; d < 64; d++)
                s += As[f * 65 + d] * Bs[d * 65 + c];
            g_Wst[(h * 64 + f) * 64 + c] = s * 0.25f;
        }
    }
}

// ---------------- CSR build ----------------
__global__ void zero_deg_kernel(int n) {
    int i = blockIdx.x * blockDim.x + threadIdx.x;
    if (i < n) g_deg[i] = 0;
}

__global__ void count_deg_kernel(const int* __restrict__ recv, int E) {
    int i = blockIdx.x * blockDim.x + threadIdx.x;
    if (i < E) atomicAdd(&g_deg[recv[i]], 1);
}

__global__ __launch_bounds__(1024) void scan_blocks_kernel(int n) {
    __shared__ int wsum[32];
    int b = blockIdx.x;
    int tid = threadIdx.x, lane = tid & 31, wid = tid >> 5;
    int i = (b << 10) + tid;
    int v = (i < n) ? g_deg[i] : 0;
    int xi = v;
    #pragma unroll
    for (int o = 1; o < 32; o <<= 1) {
        int t = __shfl_up_sync(0xffffffffu, xi, o);
        if (lane >= o) xi += t;
    }
    if (lane == 31) wsum[wid] = xi;
    __syncthreads();
    if (wid == 0) {
        int s = wsum[lane];
        #pragma unroll
        for (int o = 1; o < 32; o <<= 1) {
            int t = __shfl_up_sync(0xffffffffu, s, o);
            if (lane >= o) s += t;
        }
        wsum[lane] = s;
    }
    __syncthreads();
    int incl = xi + (wid ? wsum[wid - 1] : 0);
    if (i < n) g_rowptr[i] = incl - v;
    if (tid == 1023) g_bsum[b] = incl;
}

__global__ __launch_bounds__(32) void scan_tops_kernel(int nb, int n) {
    int lane = threadIdx.x;
    int v0 = (lane < nb) ? g_bsum[lane] : 0;
    int v1 = (lane + 32 < nb) ? g_bsum[lane + 32] : 0;
    int s0 = v0;
    #pragma unroll
    for (int o = 1; o < 32; o <<= 1) {
        int t = __shfl_up_sync(0xffffffffu, s0, o);
        if (lane >= o) s0 += t;
    }
    int tot0 = __shfl_sync(0xffffffffu, s0, 31);
    int s1 = v1;
    #pragma unroll
    for (int o = 1; o < 32; o <<= 1) {
        int t = __shfl_up_sync(0xffffffffu, s1, o);
        if (lane >= o) s1 += t;
    }
    s1 += tot0;
    g_bsumx[lane] = s0 - v0;
    g_bsumx[lane + 32] = s1 - v1;
    if (lane == 31) g_rowptr[n] = s1;
}

__global__ __launch_bounds__(1024) void scan_add_kernel(int n) {
    int i = (blockIdx.x << 10) + threadIdx.x;
    if (i < n) {
        int r = g_rowptr[i] + g_bsumx[blockIdx.x];
        g_rowptr[i] = r;
        g_cursor[i] = r;
    }
}

__global__ void scatter_edges_kernel(const int* __restrict__ send,
                                     const int* __restrict__ recv, int E) {
    int i = blockIdx.x * blockDim.x + threadIdx.x;
    if (i < E) {
        int pos = atomicAdd(&g_cursor[recv[i]], 1);
        g_esend[pos] = send[i];
    }
}

// ---------------- GEMM 1: Q' = x @ M_h, ALL 4 heads per block ----------------
// block: 128 rows, 256 threads; x tile loaded ONCE, then 4 head passes.
// inner loop = proven round-2 DUP2 form (fma-bound, movs on alu pipe).
__global__ __launch_bounds__(256) void gemm_qp_kernel(const float* __restrict__ x, int n) {
    __shared__ float As[128][64];  // x tile, 32 KB
    __shared__ float Bs[64][64];   // current head's M, 16 KB
    int row0 = blockIdx.x * 128;
    int tid = threadIdx.x;
    int rg = tid >> 4;   // 0..15 -> rows rg*8..+7
    int cg = tid & 15;   // 0..15 -> cols cg*4..+3

    for (int i = tid; i < 2048; i += 256) {
        int r = i >> 4, k4 = (i & 15) << 2;
        int gr = row0 + r;
        float4 v = make_float4(0.f, 0.f, 0.f, 0.f);
        if (gr < n) v = *reinterpret_cast<const float4*>(x + (size_t)gr * 64 + k4);
        *reinterpret_cast<float4*>(&As[r][k4]) = v;
    }

    for (int h = 0; h < HEADS; h++) {
        const float4* Bg = reinterpret_cast<const float4*>(g_M + h * 4096);
        for (int i = tid; i < 1024; i += 256)
            reinterpret_cast<float4*>(&Bs[0][0])[i] = Bg[i];
        __syncthreads();

        unsigned long long acc[8][2];
        #pragma unroll
        for (int i = 0; i < 8; i++) { acc[i][0] = 0ull; acc[i][1] = 0ull; }

        #pragma unroll 8
        for (int k = 0; k < 64; k += 2) {
            unsigned long long b00 = *reinterpret_cast<const unsigned long long*>(&Bs[k][cg << 2]);
            unsigned long long b01 = *reinterpret_cast<const unsigned long long*>(&Bs[k][(cg << 2) + 2]);
            unsigned long long b10 = *reinterpret_cast<const unsigned long long*>(&Bs[k + 1][cg << 2]);
            unsigned long long b11 = *reinterpret_cast<const unsigned long long*>(&Bs[k + 1][(cg << 2) + 2]);
            #pragma unroll
            for (int i = 0; i < 8; i++) {
                unsigned long long a2 = *reinterpret_cast<const unsigned long long*>(&As[(rg << 3) + i][k]);
                unsigned int alo, ahi;
                asm("mov.b64 {%0, %1}, %2;" : "=r"(alo), "=r"(ahi) : "l"(a2));
                unsigned long long aa0, aa1;
                DUP2(aa0, alo);
                DUP2(aa1, ahi);
                FMA2(acc[i][0], aa0, b00);
                FMA2(acc[i][1], aa0, b01);
                FMA2(acc[i][0], aa1, b10);
                FMA2(acc[i][1], aa1, b11);
            }
        }

        #pragma unroll
        for (int i = 0; i < 8; i++) {
            int gr = row0 + (rg << 3) + i;
            if (gr < n) {
                ulonglong2 o;
                o.x = acc[i][0]; o.y = acc[i][1];
                *reinterpret_cast<ulonglong2*>(g_Qp + (size_t)gr * 256 + h * 64 + (cg << 2)) = o;
            }
        }
        __syncthreads();   // protect Bs before next head's load
    }
}

// ---------------- fused attention: segment softmax (no-shift) + weighted sum ----------------
// one warp per receiver; lane l: head h=l/8, feature chunk (l%8)*8..+7.
// scores s = x_r^T M_h x_s are O(1) (|s| << 80) so unshifted exp is exact here.
__global__ __launch_bounds__(256) void attn_kernel(const float* __restrict__ x, int n) {
    int r = (blockIdx.x << 3) + (threadIdx.x >> 5);
    if (r >= n) return;
    int lane = threadIdx.x & 31;
    int j = lane & 7;

    const float4* qr = reinterpret_cast<const float4*>(g_Qp + (size_t)r * 256);
    float4 q0 = qr[lane * 2], q1 = qr[lane * 2 + 1];

    int beg = g_rowptr[r], end = g_rowptr[r + 1];
    float dsum = 0.f;
    float4 a0 = make_float4(0.f, 0.f, 0.f, 0.f);
    float4 a1 = a0;

    for (int p = beg; p < end; p++) {
        int s = g_esend[p];
        const float4* xs = reinterpret_cast<const float4*>(x + (size_t)s * 64);
        float4 v0 = xs[j * 2], v1 = xs[j * 2 + 1];

        float part = q0.x * v0.x + q0.y * v0.y + q0.z * v0.z + q0.w * v0.w
                   + q1.x * v1.x + q1.y * v1.y + q1.z * v1.z + q1.w * v1.w;
        part += __shfl_xor_sync(0xffffffffu, part, 1);
        part += __shfl_xor_sync(0xffffffffu, part, 2);
        part += __shfl_xor_sync(0xffffffffu, part, 4);

        float pe = __expf(part);
        dsum += pe;
        a0.x += pe * v0.x; a0.y += pe * v0.y; a0.z += pe * v0.z; a0.w += pe * v0.w;
        a1.x += pe * v1.x; a1.y += pe * v1.y; a1.z += pe * v1.z; a1.w += pe * v1.w;
    }

    float rinv = (dsum > 0.f) ? (1.0f / dsum) : 0.f;
    a0.x *= rinv; a0.y *= rinv; a0.z *= rinv; a0.w *= rinv;
    a1.x *= rinv; a1.y *= rinv; a1.z *= rinv; a1.w *= rinv;

    float4* tr = reinterpret_cast<float4*>(g_T + (size_t)r * 256);
    tr[lane * 2] = a0;
    tr[lane * 2 + 1] = a1;
}

// ---------------- GEMM 2: out = x + T @ Wst  (N x 256)@(256 x 64) ----------------
__global__ __launch_bounds__(256) void gemm_out_kernel(const float* __restrict__ x,
                                                       float* __restrict__ out, int n) {
    __shared__ float As[128][64];
    __shared__ float Bs[64][64];
    int row0 = blockIdx.x * 128;
    int tid = threadIdx.x;
    int rg = tid >> 4, cg = tid & 15;

    unsigned long long acc[8][2];
    #pragma unroll
    for (int i = 0; i < 8; i++) { acc[i][0] = 0ull; acc[i][1] = 0ull; }

    for (int kc = 0; kc < 4; kc++) {
        const float4* Bg = reinterpret_cast<const float4*>(g_Wst + kc * 64 * 64);
        for (int i = tid; i < 1024; i += 256)
            reinterpret_cast<float4*>(&Bs[0][0])[i] = Bg[i];
        for (int i = tid; i < 2048; i += 256) {
            int r = i >> 4, k4 = (i & 15) << 2;
            int gr = row0 + r;
            float4 v = make_float4(0.f, 0.f, 0.f, 0.f);
            if (gr < n) v = *reinterpret_cast<const float4*>(g_T + (size_t)gr * 256 + kc * 64 + k4);
            *reinterpret_cast<float4*>(&As[r][k4]) = v;
        }
        __syncthreads();

        #pragma unroll 8
        for (int k = 0; k < 64; k += 2) {
            unsigned long long b00 = *reinterpret_cast<const unsigned long long*>(&Bs[k][cg << 2]);
            unsigned long long b01 = *reinterpret_cast<const unsigned long long*>(&Bs[k][(cg << 2) + 2]);
            unsigned long long b10 = *reinterpret_cast<const unsigned long long*>(&Bs[k + 1][cg << 2]);
            unsigned long long b11 = *reinterpret_cast<const unsigned long long*>(&Bs[k + 1][(cg << 2) + 2]);
            #pragma unroll
            for (int i = 0; i < 8; i++) {
                unsigned long long a2 = *reinterpret_cast<const unsigned long long*>(&As[(rg << 3) + i][k]);
                unsigned int alo, ahi;
                asm("mov.b64 {%0, %1}, %2;" : "=r"(alo), "=r"(ahi) : "l"(a2));
                unsigned long long aa0, aa1;
                DUP2(aa0, alo);
                DUP2(aa1, ahi);
                FMA2(acc[i][0], aa0, b00);
                FMA2(acc[i][1], aa0, b01);
                FMA2(acc[i][0], aa1, b10);
                FMA2(acc[i][1], aa1, b11);
            }
        }
        __syncthreads();
    }

    #pragma unroll
    for (int i = 0; i < 8; i++) {
        int gr = row0 + (rg << 3) + i;
        if (gr < n) {
            ulonglong2 xv = *reinterpret_cast<const ulonglong2*>(x + (size_t)gr * 64 + (cg << 2));
            ulonglong2 o;
            ADD2(o.x, acc[i][0], xv.x);
            ADD2(o.y, acc[i][1], xv.y);
            *reinterpret_cast<ulonglong2*>(out + (size_t)gr * 64 + (cg << 2)) = o;
        }
    }
}

// ---------------- launch ----------------
extern "C" void kernel_launch(void* const* d_in, const int* in_sizes, int n_in,
                              void* d_out, int out_size) {
    const float* x    = (const float*)d_in[0];
    const float* Wq   = (const float*)d_in[1];
    const float* Wk   = (const float*)d_in[2];
    const float* Wv   = (const float*)d_in[3];
    const float* Wout = (const float*)d_in[4];
    const int*   ei   = (const int*)d_in[5];

    int n = in_sizes[0] / FEAT;       // 50000
    int E = in_sizes[5] / 2;          // 400000
    const int* send = ei;
    const int* recv = ei + E;
    int nb = (n + 1023) / 1024;       // 49

    prep_mats_kernel<<<8, 256>>>(Wq, Wk, Wv, Wout);

    zero_deg_kernel<<<(n + 511) / 512, 512>>>(n);
    count_deg_kernel<<<(E + 511) / 512, 512>>>(recv, E);
    scan_blocks_kernel<<<nb, 1024>>>(n);
    scan_tops_kernel<<<1, 32>>>(nb, n);
    scan_add_kernel<<<nb, 1024>>>(n);
    scatter_edges_kernel<<<(E + 511) / 512, 512>>>(send, recv, E);

    gemm_qp_kernel<<<(n + 127) / 128, 256>>>(x, n);

    attn_kernel<<<(n + 7) / 8, 256>>>(x, n);

    gemm_out_kernel<<<(n + 127) / 128, 256>>>(x, (float*)d_out, n);
}

// round 6
// speedup vs baseline: 1.3667x; 1.1398x over previous
#include <cuda_runtime.h>
#include <cstdint>

#define NNODES 50000
#define NEDGES 400000
#define FEAT   64
#define HEADS  4

// ---------------- scratch (static device globals; no allocation) ----------------
__device__ float g_Qp[(size_t)NNODES * 256];   // Q' = x @ M_h, layout [n][h*64+d]
__device__ float g_T [(size_t)NNODES * 256];   // segment-softmax-weighted sums of x_s
__device__ float g_M [HEADS * 64 * 64];        // M_h = Wq_h @ Wk_h^T * scale, [h][k][c]
__device__ float g_Wst[256 * 64];              // Wst[k][c] = (Wv@Wout)/4, k = h*64+f
__device__ uint4 g_BqpF[HEADS * 8 * 8 * 32];   // packed tf32 B frags for gemm_qp {hi0,hi1,lo0,lo1}
__device__ uint4 g_WstF[32 * 8 * 32];          // packed tf32 B frags for gemm_out
__device__ int   g_deg   [NNODES];
__device__ int   g_rowptr[NNODES + 1];
__device__ int   g_cursor[NNODES];
__device__ int   g_esend [NEDGES];
__device__ int   g_bsum  [64];
__device__ int   g_bsumx [64];

// ---------------- tf32 helpers ----------------
__device__ __forceinline__ void f2tf32_split(float v, unsigned& hi, unsigned& lo) {
    asm("cvt.rna.tf32.f32 %0, %1;" : "=r"(hi) : "f"(v));
    float l = v - __uint_as_float(hi);
    asm("cvt.rna.tf32.f32 %0, %1;" : "=r"(lo) : "f"(l));
}

#define MMA_TF32(c, a0, a1, a2, a3, b0, b1)                                          \
    asm volatile(                                                                    \
        "mma.sync.aligned.m16n8k8.row.col.f32.tf32.tf32.f32 "                        \
        "{%0,%1,%2,%3}, {%4,%5,%6,%7}, {%8,%9}, {%0,%1,%2,%3};"                      \
        : "+f"((c)[0]), "+f"((c)[1]), "+f"((c)[2]), "+f"((c)[3])                     \
        : "r"(a0), "r"(a1), "r"(a2), "r"(a3), "r"(b0), "r"(b1))

// ---------------- small matrix prep ----------------
__global__ __launch_bounds__(256) void prep_mats_kernel(
    const float* __restrict__ Wq, const float* __restrict__ Wk,
    const float* __restrict__ Wv, const float* __restrict__ Wout)
{
    __shared__ float As[64 * 65];
    __shared__ float Bs[64 * 65];
    int b = blockIdx.x;
    int tid = threadIdx.x;

    if (b < 4) {
        int h = b;
        const float* A = Wq + h * 4096;
        const float* B = Wk + h * 4096;
        for (int i = tid; i < 4096; i += 256) {
            As[(i >> 6) * 65 + (i & 63)] = A[i];
            Bs[(i >> 6) * 65 + (i & 63)] = B[i];
        }
        __syncthreads();
        for (int o = tid; o < 4096; o += 256) {
            int f1 = o & 63, f2 = o >> 6;
            float s = 0.f;
            #pragma unroll 8
            for (int d = 0; d < 64; d++)
                s += As[f1 * 65 + d] * Bs[f2 * 65 + d];
            g_M[h * 4096 + f1 * 64 + f2] = s * 0.125f;
        }
    } else {
        int h = b - 4;
        const float* A = Wv + h * 4096;
        for (int i = tid; i < 4096; i += 256) {
            As[(i >> 6) * 65 + (i & 63)] = A[i];
            Bs[(i >> 6) * 65 + (i & 63)] = Wout[i];
        }
        __syncthreads();
        for (int o = tid; o < 4096; o += 256) {
            int f = o & 63, c = o >> 6;
            float s = 0.f;
            #pragma unroll 8
            for (int d = 0; d < 64; d++)
                s += As[f * 65 + d] * Bs[d * 65 + c];
            g_Wst[(h * 64 + f) * 64 + c] = s * 0.25f;
        }
    }
}

// pack B matrices into mma-fragment order with hi/lo tf32 split.
// qp frags: tid = ((h*8 + kt)*8 + nt)*32 + lane,  0..8191
// out frags: t = ((kt*8 + nt))*32 + lane, kt 0..31, 8192..16383
__global__ __launch_bounds__(256) void pack_frags_kernel() {
    int tid = blockIdx.x * 256 + threadIdx.x;
    if (tid < 8192) {
        int lane = tid & 31;
        int nt = (tid >> 5) & 7;
        int kt = (tid >> 8) & 7;
        int h  = tid >> 11;
        int k0 = kt * 8 + (lane & 3);
        int nn = nt * 8 + (lane >> 2);
        float v0 = g_M[h * 4096 + k0 * 64 + nn];
        float v1 = g_M[h * 4096 + (k0 + 4) * 64 + nn];
        uint4 o;
        f2tf32_split(v0, o.x, o.z);
        f2tf32_split(v1, o.y, o.w);
        g_BqpF[tid] = o;
    } else if (tid < 16384) {
        int t = tid - 8192;
        int lane = t & 31;
        int nt = (t >> 5) & 7;
        int kt = t >> 8;
        int k0 = kt * 8 + (lane & 3);
        int nn = nt * 8 + (lane >> 2);
        float v0 = g_Wst[k0 * 64 + nn];
        float v1 = g_Wst[(k0 + 4) * 64 + nn];
        uint4 o;
        f2tf32_split(v0, o.x, o.z);
        f2tf32_split(v1, o.y, o.w);
        g_WstF[t] = o;
    }
}

// ---------------- CSR build ----------------
__global__ void zero_deg_kernel(int n) {
    int i = blockIdx.x * blockDim.x + threadIdx.x;
    if (i < n) g_deg[i] = 0;
}

__global__ void count_deg_kernel(const int* __restrict__ recv, int E) {
    int i = blockIdx.x * blockDim.x + threadIdx.x;
    if (i < E) atomicAdd(&g_deg[recv[i]], 1);
}

__global__ __launch_bounds__(1024) void scan_blocks_kernel(int n) {
    __shared__ int wsum[32];
    int b = blockIdx.x;
    int tid = threadIdx.x, lane = tid & 31, wid = tid >> 5;
    int i = (b << 10) + tid;
    int v = (i < n) ? g_deg[i] : 0;
    int xi = v;
    #pragma unroll
    for (int o = 1; o < 32; o <<= 1) {
        int t = __shfl_up_sync(0xffffffffu, xi, o);
        if (lane >= o) xi += t;
    }
    if (lane == 31) wsum[wid] = xi;
    __syncthreads();
    if (wid == 0) {
        int s = wsum[lane];
        #pragma unroll
        for (int o = 1; o < 32; o <<= 1) {
            int t = __shfl_up_sync(0xffffffffu, s, o);
            if (lane >= o) s += t;
        }
        wsum[lane] = s;
    }
    __syncthreads();
    int incl = xi + (wid ? wsum[wid - 1] : 0);
    if (i < n) g_rowptr[i] = incl - v;
    if (tid == 1023) g_bsum[b] = incl;
}

__global__ __launch_bounds__(32) void scan_tops_kernel(int nb, int n) {
    int lane = threadIdx.x;
    int v0 = (lane < nb) ? g_bsum[lane] : 0;
    int v1 = (lane + 32 < nb) ? g_bsum[lane + 32] : 0;
    int s0 = v0;
    #pragma unroll
    for (int o = 1; o < 32; o <<= 1) {
        int t = __shfl_up_sync(0xffffffffu, s0, o);
        if (lane >= o) s0 += t;
    }
    int tot0 = __shfl_sync(0xffffffffu, s0, 31);
    int s1 = v1;
    #pragma unroll
    for (int o = 1; o < 32; o <<= 1) {
        int t = __shfl_up_sync(0xffffffffu, s1, o);
        if (lane >= o) s1 += t;
    }
    s1 += tot0;
    g_bsumx[lane] = s0 - v0;
    g_bsumx[lane + 32] = s1 - v1;
    if (lane == 31) g_rowptr[n] = s1;
}

__global__ __launch_bounds__(1024) void scan_add_kernel(int n) {
    int i = (blockIdx.x << 10) + threadIdx.x;
    if (i < n) {
        int r = g_rowptr[i] + g_bsumx[blockIdx.x];
        g_rowptr[i] = r;
        g_cursor[i] = r;
    }
}

__global__ void scatter_edges_kernel(const int* __restrict__ send,
                                     const int* __restrict__ recv, int E) {
    int i = blockIdx.x * blockDim.x + threadIdx.x;
    if (i < E) {
        int pos = atomicAdd(&g_cursor[recv[i]], 1);
        g_esend[pos] = send[i];
    }
}

// ---------------- GEMM 1: Q' = x @ M_h  (tensor cores, 3xTF32) ----------------
// 128-row tile, 128 threads (4 warps). Warp w: rows w*32..+31 (m-tiles 2w,2w+1),
// all 8 n-tiles per head. B fragments pre-packed in gmem (L2-hot).
__global__ __launch_bounds__(128) void gemm_qp_kernel(const float* __restrict__ x, int n) {
    __shared__ float As[128][68];   // stride 68: bank-perfect for mma A-frag loads
    int row0 = blockIdx.x * 128;
    int tid = threadIdx.x, warp = tid >> 5, lane = tid & 31;
    int rq = lane >> 2, rr = lane & 3;

    for (int i = tid; i < 2048; i += 128) {
        int r = i >> 4, k4 = (i & 15) << 2;
        int gr = row0 + r;
        float4 v = make_float4(0.f, 0.f, 0.f, 0.f);
        if (gr < n) v = *reinterpret_cast<const float4*>(x + (size_t)gr * 64 + k4);
        *reinterpret_cast<float4*>(&As[r][k4]) = v;
    }
    __syncthreads();

    for (int h = 0; h < HEADS; h++) {
        float acc[2][8][4];
        #pragma unroll
        for (int mt = 0; mt < 2; mt++)
            #pragma unroll
            for (int nt = 0; nt < 8; nt++)
                #pragma unroll
                for (int q = 0; q < 4; q++) acc[mt][nt][q] = 0.f;

        #pragma unroll
        for (int kt = 0; kt < 8; kt++) {
            unsigned ah[2][4], al[2][4];
            #pragma unroll
            for (int mt = 0; mt < 2; mt++) {
                int rb = (warp << 5) + (mt << 4) + rq;
                int kb = (kt << 3) + rr;
                f2tf32_split(As[rb][kb],         ah[mt][0], al[mt][0]);
                f2tf32_split(As[rb + 8][kb],     ah[mt][1], al[mt][1]);
                f2tf32_split(As[rb][kb + 4],     ah[mt][2], al[mt][2]);
                f2tf32_split(As[rb + 8][kb + 4], ah[mt][3], al[mt][3]);
            }
            const uint4* Bf = g_BqpF + ((h * 8 + kt) * 8) * 32 + lane;
            #pragma unroll
            for (int nt = 0; nt < 8; nt++) {
                uint4 b = Bf[nt * 32];
                #pragma unroll
                for (int mt = 0; mt < 2; mt++) {
                    MMA_TF32(acc[mt][nt], ah[mt][0], ah[mt][1], ah[mt][2], ah[mt][3], b.x, b.y);
                    MMA_TF32(acc[mt][nt], al[mt][0], al[mt][1], al[mt][2], al[mt][3], b.x, b.y);
                    MMA_TF32(acc[mt][nt], ah[mt][0], ah[mt][1], ah[mt][2], ah[mt][3], b.z, b.w);
                }
            }
        }

        #pragma unroll
        for (int mt = 0; mt < 2; mt++) {
            int r0 = row0 + (warp << 5) + (mt << 4) + rq;
            #pragma unroll
            for (int nt = 0; nt < 8; nt++) {
                int c = h * 64 + nt * 8 + rr * 2;
                if (r0 < n)
                    *reinterpret_cast<float2*>(g_Qp + (size_t)r0 * 256 + c) =
                        make_float2(acc[mt][nt][0], acc[mt][nt][1]);
                if (r0 + 8 < n)
                    *reinterpret_cast<float2*>(g_Qp + (size_t)(r0 + 8) * 256 + c) =
                        make_float2(acc[mt][nt][2], acc[mt][nt][3]);
            }
        }
    }
}

// ---------------- fused attention: segment softmax (no-shift) + weighted sum ----------------
__global__ __launch_bounds__(256) void attn_kernel(const float* __restrict__ x, int n) {
    int r = (blockIdx.x << 3) + (threadIdx.x >> 5);
    if (r >= n) return;
    int lane = threadIdx.x & 31;
    int j = lane & 7;

    const float4* qr = reinterpret_cast<const float4*>(g_Qp + (size_t)r * 256);
    float4 q0 = qr[lane * 2], q1 = qr[lane * 2 + 1];

    int beg = g_rowptr[r], end = g_rowptr[r + 1];
    float dsum = 0.f;
    float4 a0 = make_float4(0.f, 0.f, 0.f, 0.f);
    float4 a1 = a0;

    for (int p = beg; p < end; p++) {
        int s = g_esend[p];
        const float4* xs = reinterpret_cast<const float4*>(x + (size_t)s * 64);
        float4 v0 = xs[j * 2], v1 = xs[j * 2 + 1];

        float part = q0.x * v0.x + q0.y * v0.y + q0.z * v0.z + q0.w * v0.w
                   + q1.x * v1.x + q1.y * v1.y + q1.z * v1.z + q1.w * v1.w;
        part += __shfl_xor_sync(0xffffffffu, part, 1);
        part += __shfl_xor_sync(0xffffffffu, part, 2);
        part += __shfl_xor_sync(0xffffffffu, part, 4);

        float pe = __expf(part);
        dsum += pe;
        a0.x += pe * v0.x; a0.y += pe * v0.y; a0.z += pe * v0.z; a0.w += pe * v0.w;
        a1.x += pe * v1.x; a1.y += pe * v1.y; a1.z += pe * v1.z; a1.w += pe * v1.w;
    }

    float rinv = (dsum > 0.f) ? (1.0f / dsum) : 0.f;
    a0.x *= rinv; a0.y *= rinv; a0.z *= rinv; a0.w *= rinv;
    a1.x *= rinv; a1.y *= rinv; a1.z *= rinv; a1.w *= rinv;

    float4* tr = reinterpret_cast<float4*>(g_T + (size_t)r * 256);
    tr[lane * 2] = a0;
    tr[lane * 2 + 1] = a1;
}

// ---------------- GEMM 2: out = x + T @ Wst  (tensor cores, 3xTF32) ----------------
__global__ __launch_bounds__(128) void gemm_out_kernel(const float* __restrict__ x,
                                                       float* __restrict__ out, int n) {
    __shared__ float As[128][68];
    int row0 = blockIdx.x * 128;
    int tid = threadIdx.x, warp = tid >> 5, lane = tid & 31;
    int rq = lane >> 2, rr = lane & 3;

    float acc[2][8][4];
    #pragma unroll
    for (int mt = 0; mt < 2; mt++)
        #pragma unroll
        for (int nt = 0; nt < 8; nt++)
            #pragma unroll
            for (int q = 0; q < 4; q++) acc[mt][nt][q] = 0.f;

    for (int kc = 0; kc < 4; kc++) {
        for (int i = tid; i < 2048; i += 128) {
            int r = i >> 4, k4 = (i & 15) << 2;
            int gr = row0 + r;
            float4 v = make_float4(0.f, 0.f, 0.f, 0.f);
            if (gr < n)
                v = *reinterpret_cast<const float4*>(g_T + (size_t)gr * 256 + kc * 64 + k4);
            *reinterpret_cast<float4*>(&As[r][k4]) = v;
        }
        __syncthreads();

        #pragma unroll
        for (int kt = 0; kt < 8; kt++) {
            unsigned ah[2][4], al[2][4];
            #pragma unroll
            for (int mt = 0; mt < 2; mt++) {
                int rb = (warp << 5) + (mt << 4) + rq;
                int kb = (kt << 3) + rr;
                f2tf32_split(As[rb][kb],         ah[mt][0], al[mt][0]);
                f2tf32_split(As[rb + 8][kb],     ah[mt][1], al[mt][1]);
                f2tf32_split(As[rb][kb + 4],     ah[mt][2], al[mt][2]);
                f2tf32_split(As[rb + 8][kb + 4], ah[mt][3], al[mt][3]);
            }
            const uint4* Bf = g_WstF + ((kc * 8 + kt) * 8) * 32 + lane;
            #pragma unroll
            for (int nt = 0; nt < 8; nt++) {
                uint4 b = Bf[nt * 32];
                #pragma unroll
                for (int mt = 0; mt < 2; mt++) {
                    MMA_TF32(acc[mt][nt], ah[mt][0], ah[mt][1], ah[mt][2], ah[mt][3], b.x, b.y);
                    MMA_TF32(acc[mt][nt], al[mt][0], al[mt][1], al[mt][2], al[mt][3], b.x, b.y);
                    MMA_TF32(acc[mt][nt], ah[mt][0], ah[mt][1], ah[mt][2], ah[mt][3], b.z, b.w);
                }
            }
        }
        __syncthreads();
    }

    #pragma unroll
    for (int mt = 0; mt < 2; mt++) {
        int r0 = row0 + (warp << 5) + (mt << 4) + rq;
        #pragma unroll
        for (int nt = 0; nt < 8; nt++) {
            int c = nt * 8 + rr * 2;
            if (r0 < n) {
                float2 xv = *reinterpret_cast<const float2*>(x + (size_t)r0 * 64 + c);
                *reinterpret_cast<float2*>(out + (size_t)r0 * 64 + c) =
                    make_float2(acc[mt][nt][0] + xv.x, acc[mt][nt][1] + xv.y);
            }
            if (r0 + 8 < n) {
                float2 xv = *reinterpret_cast<const float2*>(x + (size_t)(r0 + 8) * 64 + c);
                *reinterpret_cast<float2*>(out + (size_t)(r0 + 8) * 64 + c) =
                    make_float2(acc[mt][nt][2] + xv.x, acc[mt][nt][3] + xv.y);
            }
        }
    }
}

// ---------------- launch ----------------
extern "C" void kernel_launch(void* const* d_in, const int* in_sizes, int n_in,
                              void* d_out, int out_size) {
    const float* x    = (const float*)d_in[0];
    const float* Wq   = (const float*)d_in[1];
    const float* Wk   = (const float*)d_in[2];
    const float* Wv   = (const float*)d_in[3];
    const float* Wout = (const float*)d_in[4];
    const int*   ei   = (const int*)d_in[5];

    int n = in_sizes[0] / FEAT;       // 50000
    int E = in_sizes[5] / 2;          // 400000
    const int* send = ei;
    const int* recv = ei + E;
    int nb = (n + 1023) / 1024;       // 49

    prep_mats_kernel<<<8, 256>>>(Wq, Wk, Wv, Wout);
    pack_frags_kernel<<<64, 256>>>();

    zero_deg_kernel<<<(n + 511) / 512, 512>>>(n);
    count_deg_kernel<<<(E + 511) / 512, 512>>>(recv, E);
    scan_blocks_kernel<<<nb, 1024>>>(n);
    scan_tops_kernel<<<1, 32>>>(nb, n);
    scan_add_kernel<<<nb, 1024>>>(n);
    scatter_edges_kernel<<<(E + 511) / 512, 512>>>(send, recv, E);

    gemm_qp_kernel<<<(n + 127) / 128, 128>>>(x, n);

    attn_kernel<<<(n + 7) / 8, 256>>>(x, n);

    gemm_out_kernel<<<(n + 127) / 128, 128>>>(x, (float*)d_out, n);
}